// round 5
// baseline (speedup 1.0000x reference)
#include <cuda_runtime.h>
#include <cuda_bf16.h>
#include <cstdint>
#include <cstddef>

#define T_TOK 8192
#define HDIM  4096
#define NEXP  8
#define BM 128
#define BN 128
#define BK 16
#define KT (HDIM / BK)              // 256
#define CAP_ROWS (2 * T_TOK + NEXP * BM)   // 17408
#define MAX_TILES (CAP_ROWS / BM)          // 136
#define SSTRIDE 20                  // smem row stride (floats), conflict-free

// -------- device scratch (static; no runtime allocation) --------
__device__ float g_w[(size_t)NEXP * HDIM * HDIM];      // tf32-rounded weights
__device__ float g_xg[(size_t)CAP_ROWS * HDIM];        // grouped gathered x
__device__ float g_og[(size_t)CAP_ROWS * HDIM];        // grouped expert outputs
__device__ int g_cnt[NEXP], g_fill[NEXP], g_base[NEXP];
__device__ int g_exp0[T_TOK], g_exp1[T_TOK];
__device__ int g_pos0[T_TOK], g_pos1[T_TOK];
__device__ int g_tile_e[MAX_TILES], g_tile_r[MAX_TILES];
__device__ int g_ntiles;

// -------- helpers --------
__device__ __forceinline__ float tf32rn(float f) {
    uint32_t r;
    asm("cvt.rna.tf32.f32 %0, %1;" : "=r"(r) : "f"(f));
    return __uint_as_float(r);
}

__device__ __forceinline__ uint32_t smem_u32(const void* p) {
    uint32_t a;
    asm("{ .reg .u64 t; cvta.to.shared.u64 t, %1; cvt.u32.u64 %0, t; }"
        : "=r"(a) : "l"(p));
    return a;
}

__device__ __forceinline__ void cp16(uint32_t d, const void* s) {
    asm volatile("cp.async.cg.shared.global [%0], [%1], 16;" :: "r"(d), "l"(s));
}

__device__ __forceinline__ void mma8(float* c, const uint32_t* a, const uint32_t* b) {
    asm volatile(
        "mma.sync.aligned.m16n8k8.row.col.f32.tf32.tf32.f32 "
        "{%0,%1,%2,%3}, {%4,%5,%6,%7}, {%8,%9}, {%0,%1,%2,%3};"
        : "+f"(c[0]), "+f"(c[1]), "+f"(c[2]), "+f"(c[3])
        : "r"(a[0]), "r"(a[1]), "r"(a[2]), "r"(a[3]), "r"(b[0]), "r"(b[1]));
}

// -------- kernel 0: zero counters --------
__global__ void k_init() {
    if (threadIdx.x < NEXP) { g_cnt[threadIdx.x] = 0; g_fill[threadIdx.x] = 0; }
}

// -------- kernel 1: round expert_w to tf32-RN --------
__global__ void k_round(const float* __restrict__ w) {
    const float4* src = (const float4*)w;
    float4* dst = (float4*)g_w;
    size_t n4 = (size_t)NEXP * HDIM * HDIM / 4;   // 33554432
    size_t stride = (size_t)gridDim.x * blockDim.x;
    for (size_t i = (size_t)blockIdx.x * blockDim.x + threadIdx.x; i < n4; i += stride) {
        float4 v = src[i];
        v.x = tf32rn(v.x); v.y = tf32rn(v.y); v.z = tf32rn(v.z); v.w = tf32rn(v.w);
        dst[i] = v;
    }
}

// -------- kernel 2: gate logits + top-2 --------
__global__ void k_gate(const float* __restrict__ x, const float* __restrict__ gw) {
    int t = blockIdx.x * 8 + (threadIdx.x >> 5);
    int lane = threadIdx.x & 31;
    const float4* xr = (const float4*)(x + (size_t)t * HDIM);
    const float4* gr = (const float4*)gw;
    float acc[NEXP];
#pragma unroll
    for (int e = 0; e < NEXP; e++) acc[e] = 0.f;
    for (int i = lane; i < HDIM / 4; i += 32) {
        float4 xv = xr[i];
#pragma unroll
        for (int e = 0; e < NEXP; e++) {
            float4 wv = gr[e * (HDIM / 4) + i];
            acc[e] += xv.x * wv.x + xv.y * wv.y + xv.z * wv.z + xv.w * wv.w;
        }
    }
#pragma unroll
    for (int o = 16; o > 0; o >>= 1)
#pragma unroll
        for (int e = 0; e < NEXP; e++)
            acc[e] += __shfl_xor_sync(0xFFFFFFFFu, acc[e], o);
    if (lane == 0) {
        float v0 = -1e30f, v1 = -1e30f; int i0 = 0, i1 = 1;
#pragma unroll
        for (int e = 0; e < NEXP; e++) {
            float v = acc[e];
            if (v > v0) { v1 = v0; i1 = i0; v0 = v; i0 = e; }
            else if (v > v1) { v1 = v; i1 = e; }
        }
        g_exp0[t] = i0; g_exp1[t] = i1;
        atomicAdd(&g_cnt[i0], 1);
        atomicAdd(&g_cnt[i1], 1);
    }
}

// -------- kernel 3: prefix sum + tile map (1 thread) --------
__global__ void k_scan() {
    if (threadIdx.x != 0 || blockIdx.x != 0) return;
    int total = 0, nt = 0;
    for (int e = 0; e < NEXP; e++) {
        g_base[e] = total;
        int tl = (g_cnt[e] + BM - 1) / BM;
        for (int i = 0; i < tl; i++) { g_tile_e[nt] = e; g_tile_r[nt] = total + i * BM; nt++; }
        total += tl * BM;
    }
    g_ntiles = nt;
}

// -------- kernel 4: assign positions + gather x (tf32-RN) --------
__global__ void k_gather(const float* __restrict__ x) {
    int t = blockIdx.x;
    __shared__ int sp0, sp1;
    if (threadIdx.x == 0) {
        int e0 = g_exp0[t], e1 = g_exp1[t];
        int p0 = g_base[e0] + atomicAdd(&g_fill[e0], 1);
        int p1 = g_base[e1] + atomicAdd(&g_fill[e1], 1);
        g_pos0[t] = p0; g_pos1[t] = p1;
        sp0 = p0; sp1 = p1;
    }
    __syncthreads();
    int p0 = sp0, p1 = sp1;
    const float4* xr = (const float4*)(x + (size_t)t * HDIM);
    float4* d0 = (float4*)(g_xg + (size_t)p0 * HDIM);
    float4* d1 = (float4*)(g_xg + (size_t)p1 * HDIM);
    for (int i = threadIdx.x; i < HDIM / 4; i += blockDim.x) {
        float4 v = xr[i];
        v.x = tf32rn(v.x); v.y = tf32rn(v.y); v.z = tf32rn(v.z); v.w = tf32rn(v.w);
        d0[i] = v; d1[i] = v;
    }
}

// -------- kernel 5: grouped GEMM (tf32 mma.sync) --------
__global__ void __launch_bounds__(128) k_gemm() {
    if ((int)blockIdx.y >= g_ntiles) return;
    int e = g_tile_e[blockIdx.y];
    int row0 = g_tile_r[blockIdx.y];
    int n0 = blockIdx.x * BN;
    const float* gA = g_xg + (size_t)row0 * HDIM;
    const float* gB = g_w + (size_t)e * HDIM * HDIM + (size_t)n0 * HDIM;

    __shared__ float sA[2][BM * SSTRIDE];
    __shared__ float sB[2][BN * SSTRIDE];

    int tid = threadIdx.x, lane = tid & 31, warp = tid >> 5;
    int wm = warp >> 1, wn = warp & 1;   // 2x2 warp grid, 64x64 each

    float acc[4][8][4];
#pragma unroll
    for (int i = 0; i < 4; i++)
#pragma unroll
        for (int j = 0; j < 8; j++)
#pragma unroll
            for (int k = 0; k < 4; k++) acc[i][j][k] = 0.f;

#define LOAD_STAGE(S, K0) do {                                               \
    _Pragma("unroll")                                                        \
    for (int _i = 0; _i < 4; _i++) {                                         \
        int _c = tid + _i * 128; int _r = _c >> 2, _cc = _c & 3;             \
        cp16(smem_u32(&sA[S][_r * SSTRIDE + _cc * 4]),                       \
             gA + (size_t)_r * HDIM + (K0) + _cc * 4);                       \
        cp16(smem_u32(&sB[S][_r * SSTRIDE + _cc * 4]),                       \
             gB + (size_t)_r * HDIM + (K0) + _cc * 4);                       \
    }                                                                        \
    asm volatile("cp.async.commit_group;" ::: "memory");                     \
} while (0)

    LOAD_STAGE(0, 0);

    for (int kt = 0; kt < KT; kt++) {
        int cur = kt & 1;
        if (kt + 1 < KT) {
            LOAD_STAGE((kt + 1) & 1, (kt + 1) * BK);
            asm volatile("cp.async.wait_group 1;" ::: "memory");
        } else {
            asm volatile("cp.async.wait_group 0;" ::: "memory");
        }
        __syncthreads();

        const float* cA = sA[cur];
        const float* cB = sB[cur];
#pragma unroll
        for (int ks = 0; ks < 2; ks++) {
            int kc = ks * 8 + (lane & 3);
            uint32_t af[4][4], bf[8][2];
#pragma unroll
            for (int i = 0; i < 4; i++) {
                int rb = wm * 64 + i * 16 + (lane >> 2);
                af[i][0] = __float_as_uint(cA[rb * SSTRIDE + kc]);
                af[i][1] = __float_as_uint(cA[(rb + 8) * SSTRIDE + kc]);
                af[i][2] = __float_as_uint(cA[rb * SSTRIDE + kc + 4]);
                af[i][3] = __float_as_uint(cA[(rb + 8) * SSTRIDE + kc + 4]);
            }
#pragma unroll
            for (int j = 0; j < 8; j++) {
                int nb = wn * 64 + j * 8 + (lane >> 2);
                bf[j][0] = __float_as_uint(cB[nb * SSTRIDE + kc]);
                bf[j][1] = __float_as_uint(cB[nb * SSTRIDE + kc + 4]);
            }
#pragma unroll
            for (int i = 0; i < 4; i++)
#pragma unroll
                for (int j = 0; j < 8; j++)
                    mma8(acc[i][j], af[i], bf[j]);
        }
        __syncthreads();
    }

    float* gC = g_og + (size_t)row0 * HDIM;
#pragma unroll
    for (int i = 0; i < 4; i++) {
        int r = wm * 64 + i * 16 + (lane >> 2);
#pragma unroll
        for (int j = 0; j < 8; j++) {
            int cB0 = n0 + wn * 64 + j * 8 + 2 * (lane & 3);
            float2 v0 = make_float2(acc[i][j][0], acc[i][j][1]);
            float2 v1 = make_float2(acc[i][j][2], acc[i][j][3]);
            *(float2*)(gC + (size_t)r * HDIM + cB0) = v0;
            *(float2*)(gC + (size_t)(r + 8) * HDIM + cB0) = v1;
        }
    }
}

// -------- kernel 6: combine top-2 outputs --------
__global__ void k_combine(float* __restrict__ out) {
    int t = blockIdx.x;
    int p0 = g_pos0[t], p1 = g_pos1[t];
    const float4* a = (const float4*)(g_og + (size_t)p0 * HDIM);
    const float4* b = (const float4*)(g_og + (size_t)p1 * HDIM);
    float4* o = (float4*)(out + (size_t)t * HDIM);
    for (int i = threadIdx.x; i < HDIM / 4; i += blockDim.x) {
        float4 va = a[i], vb = b[i];
        o[i] = make_float4(va.x + vb.x, va.y + vb.y, va.z + vb.z, va.w + vb.w);
    }
}

extern "C" void kernel_launch(void* const* d_in, const int* in_sizes, int n_in,
                              void* d_out, int out_size) {
    const float* x  = (const float*)d_in[0];   // [8192, 4096]
    const float* gw = (const float*)d_in[1];   // [8, 4096]
    const float* ew = (const float*)d_in[2];   // [8, 4096, 4096]
    float* out = (float*)d_out;                // [8192, 4096]
    (void)in_sizes; (void)n_in; (void)out_size;

    k_init<<<1, 32>>>();
    k_round<<<65536, 256>>>(ew);
    k_gate<<<T_TOK / 8, 256>>>(x, gw);
    k_scan<<<1, 1>>>();
    k_gather<<<T_TOK, 128>>>(x);
    k_gemm<<<dim3(HDIM / BN, MAX_TILES), 128>>>();
    k_combine<<<T_TOK, 128>>>(out);
}

// round 7
// speedup vs baseline: 1.7967x; 1.7967x over previous
#include <cuda_runtime.h>
#include <cuda_fp16.h>
#include <cstdint>
#include <cstddef>

#define T_TOK 8192
#define HDIM  4096
#define NEXP  8
#define BM 128
#define BN 256
#define BK 32
#define KT (HDIM / BK)                       // 128
#define CAP_ROWS (2 * T_TOK + NEXP * BM)     // 17408
#define MAX_TILES (CAP_ROWS / BM)            // 136
#define SAS 40                               // smem row stride in halves (conflict-free)
#define A_STG (BM * SAS)                     // 5120 halves = 10240 B
#define B_STG (BN * SAS)                     // 10240 halves = 20480 B
#define SMEM_DYN (3 * (A_STG + B_STG) * 2)   // 92160 B

// -------- device scratch (static; no runtime allocation) --------
__device__ __half g_w[(size_t)NEXP * HDIM * HDIM];   // fp16-rounded weights
__device__ __half g_xg[(size_t)CAP_ROWS * HDIM];     // grouped gathered x (fp16)
__device__ float g_og[(size_t)CAP_ROWS * HDIM];      // grouped expert outputs
__device__ int g_cnt[NEXP], g_fill[NEXP], g_base[NEXP];
__device__ int g_exp0[T_TOK], g_exp1[T_TOK];
__device__ int g_pos0[T_TOK], g_pos1[T_TOK];
__device__ int g_tile_e[MAX_TILES], g_tile_r[MAX_TILES];
__device__ int g_ntiles;

// -------- helpers --------
__device__ __forceinline__ uint32_t smem_u32(const void* p) {
    uint32_t a;
    asm("{ .reg .u64 t; cvta.to.shared.u64 t, %1; cvt.u32.u64 %0, t; }"
        : "=r"(a) : "l"(p));
    return a;
}

__device__ __forceinline__ void cp16(uint32_t d, const void* s) {
    asm volatile("cp.async.cg.shared.global [%0], [%1], 16;" :: "r"(d), "l"(s));
}

__device__ __forceinline__ void mma16(float* c, const uint32_t* a, const uint32_t* b) {
    asm volatile(
        "mma.sync.aligned.m16n8k16.row.col.f32.f16.f16.f32 "
        "{%0,%1,%2,%3}, {%4,%5,%6,%7}, {%8,%9}, {%0,%1,%2,%3};"
        : "+f"(c[0]), "+f"(c[1]), "+f"(c[2]), "+f"(c[3])
        : "r"(a[0]), "r"(a[1]), "r"(a[2]), "r"(a[3]), "r"(b[0]), "r"(b[1]));
}

// -------- kernel 0: zero counters --------
__global__ void k_init() {
    if (threadIdx.x < NEXP) { g_cnt[threadIdx.x] = 0; g_fill[threadIdx.x] = 0; }
}

// -------- kernel 1: round expert_w to fp16 --------
__global__ void k_round(const float* __restrict__ w) {
    const float4* src = (const float4*)w;
    uint2* dst = (uint2*)g_w;
    size_t n4 = (size_t)NEXP * HDIM * HDIM / 4;
    size_t stride = (size_t)gridDim.x * blockDim.x;
    for (size_t i = (size_t)blockIdx.x * blockDim.x + threadIdx.x; i < n4; i += stride) {
        float4 v = src[i];
        __half2 h0 = __floats2half2_rn(v.x, v.y);
        __half2 h1 = __floats2half2_rn(v.z, v.w);
        uint2 o;
        o.x = *(uint32_t*)&h0;
        o.y = *(uint32_t*)&h1;
        dst[i] = o;
    }
}

// -------- kernel 2: gate logits + top-2 (fp32, fixed order) --------
__global__ void k_gate(const float* __restrict__ x, const float* __restrict__ gw) {
    int t = blockIdx.x * 8 + (threadIdx.x >> 5);
    int lane = threadIdx.x & 31;
    const float4* xr = (const float4*)(x + (size_t)t * HDIM);
    const float4* gr = (const float4*)gw;
    float acc[NEXP];
#pragma unroll
    for (int e = 0; e < NEXP; e++) acc[e] = 0.f;
    for (int i = lane; i < HDIM / 4; i += 32) {
        float4 xv = xr[i];
#pragma unroll
        for (int e = 0; e < NEXP; e++) {
            float4 wv = gr[e * (HDIM / 4) + i];
            acc[e] += xv.x * wv.x + xv.y * wv.y + xv.z * wv.z + xv.w * wv.w;
        }
    }
#pragma unroll
    for (int o = 16; o > 0; o >>= 1)
#pragma unroll
        for (int e = 0; e < NEXP; e++)
            acc[e] += __shfl_xor_sync(0xFFFFFFFFu, acc[e], o);
    if (lane == 0) {
        float v0 = -1e30f, v1 = -1e30f; int i0 = 0, i1 = 1;
#pragma unroll
        for (int e = 0; e < NEXP; e++) {
            float v = acc[e];
            if (v > v0) { v1 = v0; i1 = i0; v0 = v; i0 = e; }
            else if (v > v1) { v1 = v; i1 = e; }
        }
        g_exp0[t] = i0; g_exp1[t] = i1;
        atomicAdd(&g_cnt[i0], 1);
        atomicAdd(&g_cnt[i1], 1);
    }
}

// -------- kernel 3: prefix sum + tile map (1 thread) --------
__global__ void k_scan() {
    if (threadIdx.x != 0 || blockIdx.x != 0) return;
    int total = 0, nt = 0;
    for (int e = 0; e < NEXP; e++) {
        g_base[e] = total;
        int tl = (g_cnt[e] + BM - 1) / BM;
        for (int i = 0; i < tl; i++) { g_tile_e[nt] = e; g_tile_r[nt] = total + i * BM; nt++; }
        total += tl * BM;
    }
    g_ntiles = nt;
}

// -------- kernel 4: assign positions + gather x (fp16) --------
__global__ void k_gather(const float* __restrict__ x) {
    int t = blockIdx.x;
    __shared__ int sp0, sp1;
    if (threadIdx.x == 0) {
        int e0 = g_exp0[t], e1 = g_exp1[t];
        int p0 = g_base[e0] + atomicAdd(&g_fill[e0], 1);
        int p1 = g_base[e1] + atomicAdd(&g_fill[e1], 1);
        g_pos0[t] = p0; g_pos1[t] = p1;
        sp0 = p0; sp1 = p1;
    }
    __syncthreads();
    int p0 = sp0, p1 = sp1;
    const float4* xr = (const float4*)(x + (size_t)t * HDIM);
    uint2* d0 = (uint2*)(g_xg + (size_t)p0 * HDIM);
    uint2* d1 = (uint2*)(g_xg + (size_t)p1 * HDIM);
    for (int i = threadIdx.x; i < HDIM / 4; i += blockDim.x) {
        float4 v = xr[i];
        __half2 h0 = __floats2half2_rn(v.x, v.y);
        __half2 h1 = __floats2half2_rn(v.z, v.w);
        uint2 o;
        o.x = *(uint32_t*)&h0;
        o.y = *(uint32_t*)&h1;
        d0[i] = o; d1[i] = o;
    }
}

// -------- kernel 5: grouped GEMM, fp16 mma.sync m16n8k16, 128x256x32 --------
// 256 threads = 8 warps in a 2(M) x 4(N) grid, 64x64 per warp.
__global__ void __launch_bounds__(256, 1) k_gemm() {
    if ((int)blockIdx.y >= g_ntiles) return;
    extern __shared__ __half sm[];
    __half* sAb = sm;                  // 3 stages of A: [3][128*SAS]
    __half* sBb = sm + 3 * A_STG;      // 3 stages of B: [3][256*SAS]

    int tid = threadIdx.x, lane = tid & 31, warp = tid >> 5;
    int wm = warp >> 2, wn = warp & 3;

    int e = g_tile_e[blockIdx.y];
    int row0 = g_tile_r[blockIdx.y];
    int n0 = blockIdx.x * BN;
    const __half* gA = g_xg + (size_t)row0 * HDIM;
    const __half* gB = g_w + (size_t)e * HDIM * HDIM + (size_t)n0 * HDIM;

    float acc[4][8][4];
#pragma unroll
    for (int i = 0; i < 4; i++)
#pragma unroll
        for (int j = 0; j < 8; j++)
#pragma unroll
            for (int k = 0; k < 4; k++) acc[i][j][k] = 0.f;

#define LOAD_STAGE(S, K0) do {                                               \
    __half* _sa = sAb + (S) * A_STG;                                         \
    __half* _sb = sBb + (S) * B_STG;                                         \
    const __half* _ga = gA + (K0);                                           \
    const __half* _gb = gB + (K0);                                           \
    _Pragma("unroll")                                                        \
    for (int _i = 0; _i < 2; _i++) {          /* A: 512 x 16B chunks */      \
        int _ch = tid + _i * 256; int _r = _ch >> 2, _c = _ch & 3;           \
        cp16(smem_u32(_sa + _r * SAS + _c * 8), _ga + (size_t)_r * HDIM + _c * 8); \
    }                                                                        \
    _Pragma("unroll")                                                        \
    for (int _i = 0; _i < 4; _i++) {          /* B: 1024 x 16B chunks */     \
        int _ch = tid + _i * 256; int _r = _ch >> 2, _c = _ch & 3;           \
        cp16(smem_u32(_sb + _r * SAS + _c * 8), _gb + (size_t)_r * HDIM + _c * 8); \
    }                                                                        \
    asm volatile("cp.async.commit_group;" ::: "memory");                     \
} while (0)

    LOAD_STAGE(0, 0);
    LOAD_STAGE(1, BK);

    for (int kt = 0; kt < KT; kt++) {
        if (kt + 1 == KT) asm volatile("cp.async.wait_group 0;" ::: "memory");
        else              asm volatile("cp.async.wait_group 1;" ::: "memory");
        __syncthreads();

        int cur = kt % 3;
        const __half* cA = sAb + cur * A_STG;
        const __half* cB = sBb + cur * B_STG;
#pragma unroll
        for (int ks = 0; ks < 2; ks++) {
            int kc = ks * 16 + (lane & 3) * 2;
            uint32_t af[4][4], bf[8][2];
#pragma unroll
            for (int i = 0; i < 4; i++) {
                int rb = wm * 64 + i * 16 + (lane >> 2);
                af[i][0] = *(const uint32_t*)&cA[rb * SAS + kc];
                af[i][1] = *(const uint32_t*)&cA[(rb + 8) * SAS + kc];
                af[i][2] = *(const uint32_t*)&cA[rb * SAS + kc + 8];
                af[i][3] = *(const uint32_t*)&cA[(rb + 8) * SAS + kc + 8];
            }
#pragma unroll
            for (int j = 0; j < 8; j++) {
                int nb = wn * 64 + j * 8 + (lane >> 2);
                bf[j][0] = *(const uint32_t*)&cB[nb * SAS + kc];
                bf[j][1] = *(const uint32_t*)&cB[nb * SAS + kc + 8];
            }
#pragma unroll
            for (int i = 0; i < 4; i++)
#pragma unroll
                for (int j = 0; j < 8; j++)
                    mma16(acc[i][j], af[i], bf[j]);
        }

        if (kt + 2 < KT) LOAD_STAGE((kt + 2) % 3, (kt + 2) * BK);
    }

    // epilogue: registers -> g_og (fp32)
    float* gC = g_og + (size_t)row0 * HDIM;
#pragma unroll
    for (int i = 0; i < 4; i++) {
        int r = wm * 64 + i * 16 + (lane >> 2);
#pragma unroll
        for (int j = 0; j < 8; j++) {
            int c0 = n0 + wn * 64 + j * 8 + 2 * (lane & 3);
            *(float2*)(gC + (size_t)r * HDIM + c0) = make_float2(acc[i][j][0], acc[i][j][1]);
            *(float2*)(gC + (size_t)(r + 8) * HDIM + c0) = make_float2(acc[i][j][2], acc[i][j][3]);
        }
    }
#undef LOAD_STAGE
}

// -------- kernel 6: combine top-2 outputs --------
__global__ void k_combine(float* __restrict__ out) {
    int t = blockIdx.x;
    int p0 = g_pos0[t], p1 = g_pos1[t];
    const float4* a = (const float4*)(g_og + (size_t)p0 * HDIM);
    const float4* b = (const float4*)(g_og + (size_t)p1 * HDIM);
    float4* o = (float4*)(out + (size_t)t * HDIM);
    for (int i = threadIdx.x; i < HDIM / 4; i += blockDim.x) {
        float4 va = a[i], vb = b[i];
        o[i] = make_float4(va.x + vb.x, va.y + vb.y, va.z + vb.z, va.w + vb.w);
    }
}

extern "C" void kernel_launch(void* const* d_in, const int* in_sizes, int n_in,
                              void* d_out, int out_size) {
    const float* x  = (const float*)d_in[0];   // [8192, 4096]
    const float* gw = (const float*)d_in[1];   // [8, 4096]
    const float* ew = (const float*)d_in[2];   // [8, 4096, 4096]
    float* out = (float*)d_out;                // [8192, 4096]
    (void)in_sizes; (void)n_in; (void)out_size;

    cudaFuncSetAttribute(k_gemm, cudaFuncAttributeMaxDynamicSharedMemorySize, SMEM_DYN);

    k_init<<<1, 32>>>();
    k_round<<<65536, 256>>>(ew);
    k_gate<<<T_TOK / 8, 256>>>(x, gw);
    k_scan<<<1, 1>>>();
    k_gather<<<T_TOK, 128>>>(x);
    k_gemm<<<dim3(HDIM / BN, MAX_TILES), 256, SMEM_DYN>>>();
    k_combine<<<T_TOK, 128>>>(out);
}

// round 8
// speedup vs baseline: 2.0080x; 1.1176x over previous
#include <cuda_runtime.h>
#include <cuda_fp16.h>
#include <cstdint>
#include <cstddef>

#define T_TOK 8192
#define HDIM  4096
#define NEXP  8
#define BM 128
#define BN 256
#define BK 32
#define KT (HDIM / BK)                       // 128
#define CAP_ROWS (2 * T_TOK + NEXP * BM)     // 17408
#define MAX_TILES (CAP_ROWS / BM)            // 136
#define SAS 40                               // smem row stride in halves (conflict-free)
#define A_STG (BM * SAS)                     // 5120 halves
#define B_STG (BN * SAS)                     // 10240 halves
#define SMEM_DYN (3 * (A_STG + B_STG) * 2)   // 92160 B

// -------- device scratch (static; no runtime allocation) --------
__device__ __half g_w[(size_t)NEXP * HDIM * HDIM];   // fp16-rounded weights
__device__ __half g_xg[(size_t)CAP_ROWS * HDIM];     // grouped gathered x (fp16)
__device__ float g_og[(size_t)CAP_ROWS * HDIM];      // grouped expert outputs
__device__ int g_cnt[NEXP], g_fill[NEXP], g_base[NEXP];
__device__ int g_exp0[T_TOK], g_exp1[T_TOK];
__device__ int g_pos0[T_TOK], g_pos1[T_TOK];
__device__ int g_tile_e[MAX_TILES], g_tile_r[MAX_TILES];
__device__ int g_ntiles;

// -------- helpers --------
__device__ __forceinline__ uint32_t smem_u32(const void* p) {
    uint32_t a;
    asm("{ .reg .u64 t; cvta.to.shared.u64 t, %1; cvt.u32.u64 %0, t; }"
        : "=r"(a) : "l"(p));
    return a;
}

__device__ __forceinline__ void cp16(uint32_t d, const void* s) {
    asm volatile("cp.async.cg.shared.global [%0], [%1], 16;" :: "r"(d), "l"(s));
}

__device__ __forceinline__ void mma16(float* c, const uint32_t* a, const uint32_t* b) {
    asm volatile(
        "mma.sync.aligned.m16n8k16.row.col.f32.f16.f16.f32 "
        "{%0,%1,%2,%3}, {%4,%5,%6,%7}, {%8,%9}, {%0,%1,%2,%3};"
        : "+f"(c[0]), "+f"(c[1]), "+f"(c[2]), "+f"(c[3])
        : "r"(a[0]), "r"(a[1]), "r"(a[2]), "r"(a[3]), "r"(b[0]), "r"(b[1]));
}

__device__ __forceinline__ void ldm4(uint32_t* r, uint32_t addr) {
    asm volatile("ldmatrix.sync.aligned.m8n8.x4.shared.b16 {%0,%1,%2,%3}, [%4];"
                 : "=r"(r[0]), "=r"(r[1]), "=r"(r[2]), "=r"(r[3]) : "r"(addr));
}

// -------- kernel 0: zero counters --------
__global__ void k_init() {
    if (threadIdx.x < NEXP) { g_cnt[threadIdx.x] = 0; g_fill[threadIdx.x] = 0; }
}

// -------- kernel 1: round expert_w to fp16 --------
__global__ void k_round(const float* __restrict__ w) {
    const float4* src = (const float4*)w;
    uint2* dst = (uint2*)g_w;
    size_t n4 = (size_t)NEXP * HDIM * HDIM / 4;
    size_t stride = (size_t)gridDim.x * blockDim.x;
    for (size_t i = (size_t)blockIdx.x * blockDim.x + threadIdx.x; i < n4; i += stride) {
        float4 v = src[i];
        __half2 h0 = __floats2half2_rn(v.x, v.y);
        __half2 h1 = __floats2half2_rn(v.z, v.w);
        uint2 o;
        o.x = *(uint32_t*)&h0;
        o.y = *(uint32_t*)&h1;
        dst[i] = o;
    }
}

// -------- kernel 2: gate logits + top-2 (fp32, fixed order) --------
__global__ void k_gate(const float* __restrict__ x, const float* __restrict__ gw) {
    int t = blockIdx.x * 8 + (threadIdx.x >> 5);
    int lane = threadIdx.x & 31;
    const float4* xr = (const float4*)(x + (size_t)t * HDIM);
    const float4* gr = (const float4*)gw;
    float acc[NEXP];
#pragma unroll
    for (int e = 0; e < NEXP; e++) acc[e] = 0.f;
    for (int i = lane; i < HDIM / 4; i += 32) {
        float4 xv = xr[i];
#pragma unroll
        for (int e = 0; e < NEXP; e++) {
            float4 wv = gr[e * (HDIM / 4) + i];
            acc[e] += xv.x * wv.x + xv.y * wv.y + xv.z * wv.z + xv.w * wv.w;
        }
    }
#pragma unroll
    for (int o = 16; o > 0; o >>= 1)
#pragma unroll
        for (int e = 0; e < NEXP; e++)
            acc[e] += __shfl_xor_sync(0xFFFFFFFFu, acc[e], o);
    if (lane == 0) {
        float v0 = -1e30f, v1 = -1e30f; int i0 = 0, i1 = 1;
#pragma unroll
        for (int e = 0; e < NEXP; e++) {
            float v = acc[e];
            if (v > v0) { v1 = v0; i1 = i0; v0 = v; i0 = e; }
            else if (v > v1) { v1 = v; i1 = e; }
        }
        g_exp0[t] = i0; g_exp1[t] = i1;
        atomicAdd(&g_cnt[i0], 1);
        atomicAdd(&g_cnt[i1], 1);
    }
}

// -------- kernel 3: prefix sum + tile map (1 thread) --------
__global__ void k_scan() {
    if (threadIdx.x != 0 || blockIdx.x != 0) return;
    int total = 0, nt = 0;
    for (int e = 0; e < NEXP; e++) {
        g_base[e] = total;
        int tl = (g_cnt[e] + BM - 1) / BM;
        for (int i = 0; i < tl; i++) { g_tile_e[nt] = e; g_tile_r[nt] = total + i * BM; nt++; }
        total += tl * BM;
    }
    g_ntiles = nt;
}

// -------- kernel 4: assign positions + gather x (fp16) --------
__global__ void k_gather(const float* __restrict__ x) {
    int t = blockIdx.x;
    __shared__ int sp0, sp1;
    if (threadIdx.x == 0) {
        int e0 = g_exp0[t], e1 = g_exp1[t];
        int p0 = g_base[e0] + atomicAdd(&g_fill[e0], 1);
        int p1 = g_base[e1] + atomicAdd(&g_fill[e1], 1);
        g_pos0[t] = p0; g_pos1[t] = p1;
        sp0 = p0; sp1 = p1;
    }
    __syncthreads();
    int p0 = sp0, p1 = sp1;
    const float4* xr = (const float4*)(x + (size_t)t * HDIM);
    uint2* d0 = (uint2*)(g_xg + (size_t)p0 * HDIM);
    uint2* d1 = (uint2*)(g_xg + (size_t)p1 * HDIM);
    for (int i = threadIdx.x; i < HDIM / 4; i += blockDim.x) {
        float4 v = xr[i];
        __half2 h0 = __floats2half2_rn(v.x, v.y);
        __half2 h1 = __floats2half2_rn(v.z, v.w);
        uint2 o;
        o.x = *(uint32_t*)&h0;
        o.y = *(uint32_t*)&h1;
        d0[i] = o; d1[i] = o;
    }
}

// -------- kernel 5: grouped GEMM, fp16 m16n8k16 + ldmatrix, 128x256x32 --------
// 256 threads = 8 warps in a 2(M) x 4(N) grid, 64x64 per warp.
__global__ void __launch_bounds__(256, 1) k_gemm() {
    if ((int)blockIdx.y >= g_ntiles) return;
    extern __shared__ __half sm[];
    __half* sAb = sm;                  // 3 stages of A
    __half* sBb = sm + 3 * A_STG;      // 3 stages of B

    int tid = threadIdx.x, lane = tid & 31, warp = tid >> 5;
    int wm = warp >> 2, wn = warp & 3;

    int e = g_tile_e[blockIdx.y];
    int row0 = g_tile_r[blockIdx.y];
    int n0 = blockIdx.x * BN;
    const __half* gA = g_xg + (size_t)row0 * HDIM;
    const __half* gB = g_w + (size_t)e * HDIM * HDIM + (size_t)n0 * HDIM;

    // per-lane ldmatrix offsets (in halves)
    // A x4: lanes 0-15 -> rows 0..15 col+0; lanes 16-31 -> rows 0..15 col+8
    int aOff = (wm * 64 + (lane & 15)) * SAS + (lane >> 4) * 8;
    // B x4: m0=(j rows,k0) m1=(j rows,k+8) m2=(j+1 rows,k0) m3=(j+1 rows,k+8)
    int bOff = (wn * 64 + (lane & 7) + ((lane >> 4) << 3)) * SAS + (((lane >> 3) & 1) << 3);

    float acc[4][8][4];
#pragma unroll
    for (int i = 0; i < 4; i++)
#pragma unroll
        for (int j = 0; j < 8; j++)
#pragma unroll
            for (int k = 0; k < 4; k++) acc[i][j][k] = 0.f;

#define LOAD_STAGE(S, K0) do {                                               \
    __half* _sa = sAb + (S) * A_STG;                                         \
    __half* _sb = sBb + (S) * B_STG;                                         \
    const __half* _ga = gA + (K0);                                           \
    const __half* _gb = gB + (K0);                                           \
    _Pragma("unroll")                                                        \
    for (int _i = 0; _i < 2; _i++) {                                         \
        int _ch = tid + _i * 256; int _r = _ch >> 2, _c = _ch & 3;           \
        cp16(smem_u32(_sa + _r * SAS + _c * 8), _ga + (size_t)_r * HDIM + _c * 8); \
    }                                                                        \
    _Pragma("unroll")                                                        \
    for (int _i = 0; _i < 4; _i++) {                                         \
        int _ch = tid + _i * 256; int _r = _ch >> 2, _c = _ch & 3;           \
        cp16(smem_u32(_sb + _r * SAS + _c * 8), _gb + (size_t)_r * HDIM + _c * 8); \
    }                                                                        \
    asm volatile("cp.async.commit_group;" ::: "memory");                     \
} while (0)

    LOAD_STAGE(0, 0);
    LOAD_STAGE(1, BK);

    for (int kt = 0; kt < KT; kt++) {
        if (kt + 1 == KT) asm volatile("cp.async.wait_group 0;" ::: "memory");
        else              asm volatile("cp.async.wait_group 1;" ::: "memory");
        __syncthreads();

        int cur = kt % 3;
        uint32_t aBase = smem_u32(sAb + cur * A_STG + aOff);
        uint32_t bBase = smem_u32(sBb + cur * B_STG + bOff);
#pragma unroll
        for (int ks = 0; ks < 2; ks++) {
            uint32_t af[4][4], bf[8][2];
#pragma unroll
            for (int i = 0; i < 4; i++)
                ldm4(af[i], aBase + (i * 16 * SAS + ks * 16) * 2);
#pragma unroll
            for (int jj = 0; jj < 4; jj++) {
                uint32_t r[4];
                ldm4(r, bBase + (jj * 16 * SAS + ks * 16) * 2);
                bf[2 * jj][0] = r[0]; bf[2 * jj][1] = r[1];
                bf[2 * jj + 1][0] = r[2]; bf[2 * jj + 1][1] = r[3];
            }
#pragma unroll
            for (int i = 0; i < 4; i++)
#pragma unroll
                for (int j = 0; j < 8; j++)
                    mma16(acc[i][j], af[i], bf[j]);
        }

        if (kt + 2 < KT) LOAD_STAGE((kt + 2) % 3, (kt + 2) * BK);
    }

    // epilogue: registers -> g_og (fp32)
    float* gC = g_og + (size_t)row0 * HDIM;
#pragma unroll
    for (int i = 0; i < 4; i++) {
        int r = wm * 64 + i * 16 + (lane >> 2);
#pragma unroll
        for (int j = 0; j < 8; j++) {
            int c0 = n0 + wn * 64 + j * 8 + 2 * (lane & 3);
            *(float2*)(gC + (size_t)r * HDIM + c0) = make_float2(acc[i][j][0], acc[i][j][1]);
            *(float2*)(gC + (size_t)(r + 8) * HDIM + c0) = make_float2(acc[i][j][2], acc[i][j][3]);
        }
    }
#undef LOAD_STAGE
}

// -------- kernel 6: combine top-2 outputs --------
__global__ void k_combine(float* __restrict__ out) {
    int t = blockIdx.x;
    int p0 = g_pos0[t], p1 = g_pos1[t];
    const float4* a = (const float4*)(g_og + (size_t)p0 * HDIM);
    const float4* b = (const float4*)(g_og + (size_t)p1 * HDIM);
    float4* o = (float4*)(out + (size_t)t * HDIM);
    for (int i = threadIdx.x; i < HDIM / 4; i += blockDim.x) {
        float4 va = a[i], vb = b[i];
        o[i] = make_float4(va.x + vb.x, va.y + vb.y, va.z + vb.z, va.w + vb.w);
    }
}

extern "C" void kernel_launch(void* const* d_in, const int* in_sizes, int n_in,
                              void* d_out, int out_size) {
    const float* x  = (const float*)d_in[0];   // [8192, 4096]
    const float* gw = (const float*)d_in[1];   // [8, 4096]
    const float* ew = (const float*)d_in[2];   // [8, 4096, 4096]
    float* out = (float*)d_out;                // [8192, 4096]
    (void)in_sizes; (void)n_in; (void)out_size;

    cudaFuncSetAttribute(k_gemm, cudaFuncAttributeMaxDynamicSharedMemorySize, SMEM_DYN);

    k_init<<<1, 32>>>();
    k_round<<<65536, 256>>>(ew);
    k_gate<<<T_TOK / 8, 256>>>(x, gw);
    k_scan<<<1, 1>>>();
    k_gather<<<T_TOK, 128>>>(x);
    k_gemm<<<dim3(HDIM / BN, MAX_TILES), 256, SMEM_DYN>>>();
    k_combine<<<T_TOK, 128>>>(out);
}

// round 9
// speedup vs baseline: 2.1507x; 1.0711x over previous
#include <cuda_runtime.h>
#include <cuda_fp16.h>
#include <cstdint>
#include <cstddef>

#define T_TOK 8192
#define HDIM  4096
#define NEXP  8
#define BM 128
#define BN 256
#define BK 64
#define KT (HDIM / BK)                       // 64
#define CAP_ROWS (2 * T_TOK + NEXP * BM)     // 17408
#define MAX_TILES (CAP_ROWS / BM)            // 136
#define SAS 72                               // smem row stride in halves (64 data + 8 pad)
#define A_STG (BM * SAS)                     // 9216 halves
#define B_STG (BN * SAS)                     // 18432 halves
#define SMEM_DYN (3 * (A_STG + B_STG) * 2)   // 165888 B

// -------- device scratch (static; no runtime allocation) --------
__device__ __half g_w[(size_t)NEXP * HDIM * HDIM];   // fp16-rounded weights
__device__ __half g_xg[(size_t)CAP_ROWS * HDIM];     // grouped gathered x (fp16)
__device__ int g_cnt[NEXP], g_fill[NEXP], g_base[NEXP];
__device__ int g_exp0[T_TOK], g_exp1[T_TOK];
__device__ int g_rowtok[CAP_ROWS];                   // grouped row -> token (-1 = pad)
__device__ int g_tile_e[MAX_TILES], g_tile_r[MAX_TILES];
__device__ int g_ntiles;

// -------- helpers --------
__device__ __forceinline__ uint32_t smem_u32(const void* p) {
    uint32_t a;
    asm("{ .reg .u64 t; cvta.to.shared.u64 t, %1; cvt.u32.u64 %0, t; }"
        : "=r"(a) : "l"(p));
    return a;
}

__device__ __forceinline__ void cp16(uint32_t d, const void* s) {
    asm volatile("cp.async.cg.shared.global [%0], [%1], 16;" :: "r"(d), "l"(s));
}

__device__ __forceinline__ void mma16(float* c, const uint32_t* a, const uint32_t* b) {
    asm volatile(
        "mma.sync.aligned.m16n8k16.row.col.f32.f16.f16.f32 "
        "{%0,%1,%2,%3}, {%4,%5,%6,%7}, {%8,%9}, {%0,%1,%2,%3};"
        : "+f"(c[0]), "+f"(c[1]), "+f"(c[2]), "+f"(c[3])
        : "r"(a[0]), "r"(a[1]), "r"(a[2]), "r"(a[3]), "r"(b[0]), "r"(b[1]));
}

__device__ __forceinline__ void ldm4(uint32_t* r, uint32_t addr) {
    asm volatile("ldmatrix.sync.aligned.m8n8.x4.shared.b16 {%0,%1,%2,%3}, [%4];"
                 : "=r"(r[0]), "=r"(r[1]), "=r"(r[2]), "=r"(r[3]) : "r"(addr));
}

__device__ __forceinline__ void red2(float* p, float a, float b) {
    asm volatile("red.global.add.f32 [%0], %1;" :: "l"(p), "f"(a) : "memory");
    asm volatile("red.global.add.f32 [%0], %1;" :: "l"(p + 1), "f"(b) : "memory");
}

// -------- kernel 0: zero counters + rowtok --------
__global__ void k_init() {
    int i = blockIdx.x * blockDim.x + threadIdx.x;
    if (i < NEXP) { g_cnt[i] = 0; g_fill[i] = 0; }
    if (i < CAP_ROWS) g_rowtok[i] = -1;
}

// -------- kernel 1: round expert_w to fp16 --------
__global__ void k_round(const float* __restrict__ w) {
    const float4* src = (const float4*)w;
    uint2* dst = (uint2*)g_w;
    size_t n4 = (size_t)NEXP * HDIM * HDIM / 4;
    size_t stride = (size_t)gridDim.x * blockDim.x;
    for (size_t i = (size_t)blockIdx.x * blockDim.x + threadIdx.x; i < n4; i += stride) {
        float4 v = src[i];
        __half2 h0 = __floats2half2_rn(v.x, v.y);
        __half2 h1 = __floats2half2_rn(v.z, v.w);
        uint2 o;
        o.x = *(uint32_t*)&h0;
        o.y = *(uint32_t*)&h1;
        dst[i] = o;
    }
}

// -------- kernel 2: gate logits + top-2 (fp32, fixed order) --------
__global__ void k_gate(const float* __restrict__ x, const float* __restrict__ gw) {
    int t = blockIdx.x * 8 + (threadIdx.x >> 5);
    int lane = threadIdx.x & 31;
    const float4* xr = (const float4*)(x + (size_t)t * HDIM);
    const float4* gr = (const float4*)gw;
    float acc[NEXP];
#pragma unroll
    for (int e = 0; e < NEXP; e++) acc[e] = 0.f;
    for (int i = lane; i < HDIM / 4; i += 32) {
        float4 xv = xr[i];
#pragma unroll
        for (int e = 0; e < NEXP; e++) {
            float4 wv = gr[e * (HDIM / 4) + i];
            acc[e] += xv.x * wv.x + xv.y * wv.y + xv.z * wv.z + xv.w * wv.w;
        }
    }
#pragma unroll
    for (int o = 16; o > 0; o >>= 1)
#pragma unroll
        for (int e = 0; e < NEXP; e++)
            acc[e] += __shfl_xor_sync(0xFFFFFFFFu, acc[e], o);
    if (lane == 0) {
        float v0 = -1e30f, v1 = -1e30f; int i0 = 0, i1 = 1;
#pragma unroll
        for (int e = 0; e < NEXP; e++) {
            float v = acc[e];
            if (v > v0) { v1 = v0; i1 = i0; v0 = v; i0 = e; }
            else if (v > v1) { v1 = v; i1 = e; }
        }
        g_exp0[t] = i0; g_exp1[t] = i1;
        atomicAdd(&g_cnt[i0], 1);
        atomicAdd(&g_cnt[i1], 1);
    }
}

// -------- kernel 3: prefix sum + tile map (1 thread) --------
__global__ void k_scan() {
    if (threadIdx.x != 0 || blockIdx.x != 0) return;
    int total = 0, nt = 0;
    for (int e = 0; e < NEXP; e++) {
        g_base[e] = total;
        int tl = (g_cnt[e] + BM - 1) / BM;
        for (int i = 0; i < tl; i++) { g_tile_e[nt] = e; g_tile_r[nt] = total + i * BM; nt++; }
        total += tl * BM;
    }
    g_ntiles = nt;
}

// -------- kernel 4: assign positions + gather x (fp16) --------
__global__ void k_gather(const float* __restrict__ x) {
    int t = blockIdx.x;
    __shared__ int sp0, sp1;
    if (threadIdx.x == 0) {
        int e0 = g_exp0[t], e1 = g_exp1[t];
        int p0 = g_base[e0] + atomicAdd(&g_fill[e0], 1);
        int p1 = g_base[e1] + atomicAdd(&g_fill[e1], 1);
        g_rowtok[p0] = t; g_rowtok[p1] = t;
        sp0 = p0; sp1 = p1;
    }
    __syncthreads();
    int p0 = sp0, p1 = sp1;
    const float4* xr = (const float4*)(x + (size_t)t * HDIM);
    uint2* d0 = (uint2*)(g_xg + (size_t)p0 * HDIM);
    uint2* d1 = (uint2*)(g_xg + (size_t)p1 * HDIM);
    for (int i = threadIdx.x; i < HDIM / 4; i += blockDim.x) {
        float4 v = xr[i];
        __half2 h0 = __floats2half2_rn(v.x, v.y);
        __half2 h1 = __floats2half2_rn(v.z, v.w);
        uint2 o;
        o.x = *(uint32_t*)&h0;
        o.y = *(uint32_t*)&h1;
        d0[i] = o; d1[i] = o;
    }
}

// -------- kernel 5: grouped GEMM, fp16 m16n8k16 + ldmatrix, 128x256x64 --------
// 256 threads = 8 warps in a 2(M) x 4(N) grid, 64x64 per warp.
// Epilogue scatter-reduces directly into out (2 deterministic adds per element).
__global__ void __launch_bounds__(256, 1) k_gemm(float* __restrict__ out) {
    if ((int)blockIdx.y >= g_ntiles) return;
    extern __shared__ __half sm[];
    __half* sAb = sm;                  // 3 stages of A
    __half* sBb = sm + 3 * A_STG;      // 3 stages of B

    int tid = threadIdx.x, lane = tid & 31, warp = tid >> 5;
    int wm = warp >> 2, wn = warp & 3;

    int e = g_tile_e[blockIdx.y];
    int row0 = g_tile_r[blockIdx.y];
    int n0 = blockIdx.x * BN;
    const __half* gA = g_xg + (size_t)row0 * HDIM;
    const __half* gB = g_w + (size_t)e * HDIM * HDIM + (size_t)n0 * HDIM;

    // per-lane ldmatrix offsets (in halves)
    int aOff = (wm * 64 + (lane & 15)) * SAS + (lane >> 4) * 8;
    int bOff = (wn * 64 + (lane & 7) + ((lane >> 4) << 3)) * SAS + (((lane >> 3) & 1) << 3);

    float acc[4][8][4];
#pragma unroll
    for (int i = 0; i < 4; i++)
#pragma unroll
        for (int j = 0; j < 8; j++)
#pragma unroll
            for (int k = 0; k < 4; k++) acc[i][j][k] = 0.f;

#define LOAD_STAGE(S, K0) do {                                               \
    __half* _sa = sAb + (S) * A_STG;                                         \
    __half* _sb = sBb + (S) * B_STG;                                         \
    const __half* _ga = gA + (K0);                                           \
    const __half* _gb = gB + (K0);                                           \
    _Pragma("unroll")                                                        \
    for (int _i = 0; _i < 4; _i++) {      /* A: 1024 x 16B chunks */         \
        int _ch = tid + _i * 256; int _r = _ch >> 3, _c = _ch & 7;           \
        cp16(smem_u32(_sa + _r * SAS + _c * 8), _ga + (size_t)_r * HDIM + _c * 8); \
    }                                                                        \
    _Pragma("unroll")                                                        \
    for (int _i = 0; _i < 8; _i++) {      /* B: 2048 x 16B chunks */         \
        int _ch = tid + _i * 256; int _r = _ch >> 3, _c = _ch & 7;           \
        cp16(smem_u32(_sb + _r * SAS + _c * 8), _gb + (size_t)_r * HDIM + _c * 8); \
    }                                                                        \
    asm volatile("cp.async.commit_group;" ::: "memory");                     \
} while (0)

    LOAD_STAGE(0, 0);
    LOAD_STAGE(1, BK);

    for (int kt = 0; kt < KT; kt++) {
        if (kt + 1 == KT) asm volatile("cp.async.wait_group 0;" ::: "memory");
        else              asm volatile("cp.async.wait_group 1;" ::: "memory");
        __syncthreads();

        int cur = kt % 3;
        uint32_t aBase = smem_u32(sAb + cur * A_STG + aOff);
        uint32_t bBase = smem_u32(sBb + cur * B_STG + bOff);
#pragma unroll
        for (int ks = 0; ks < 4; ks++) {
            uint32_t af[4][4], bf[8][2];
#pragma unroll
            for (int i = 0; i < 4; i++)
                ldm4(af[i], aBase + (i * 16 * SAS + ks * 16) * 2);
#pragma unroll
            for (int jj = 0; jj < 4; jj++) {
                uint32_t r[4];
                ldm4(r, bBase + (jj * 16 * SAS + ks * 16) * 2);
                bf[2 * jj][0] = r[0]; bf[2 * jj][1] = r[1];
                bf[2 * jj + 1][0] = r[2]; bf[2 * jj + 1][1] = r[3];
            }
#pragma unroll
            for (int i = 0; i < 4; i++)
#pragma unroll
                for (int j = 0; j < 8; j++)
                    mma16(acc[i][j], af[i], bf[j]);
        }

        if (kt + 2 < KT) LOAD_STAGE((kt + 2) % 3, (kt + 2) * BK);
    }

    // epilogue: scatter-reduce rows into out by token (pad rows skipped)
#pragma unroll
    for (int i = 0; i < 4; i++) {
        int rl = wm * 64 + i * 16 + (lane >> 2);
        int tok0 = g_rowtok[row0 + rl];
        int tok1 = g_rowtok[row0 + rl + 8];
        float* o0 = out + (size_t)tok0 * HDIM;
        float* o1 = out + (size_t)tok1 * HDIM;
#pragma unroll
        for (int j = 0; j < 8; j++) {
            int c0 = n0 + wn * 64 + j * 8 + 2 * (lane & 3);
            if (tok0 >= 0) red2(o0 + c0, acc[i][j][0], acc[i][j][1]);
            if (tok1 >= 0) red2(o1 + c0, acc[i][j][2], acc[i][j][3]);
        }
    }
#undef LOAD_STAGE
}

extern "C" void kernel_launch(void* const* d_in, const int* in_sizes, int n_in,
                              void* d_out, int out_size) {
    const float* x  = (const float*)d_in[0];   // [8192, 4096]
    const float* gw = (const float*)d_in[1];   // [8, 4096]
    const float* ew = (const float*)d_in[2];   // [8, 4096, 4096]
    float* out = (float*)d_out;                // [8192, 4096]
    (void)in_sizes; (void)n_in; (void)out_size;

    cudaFuncSetAttribute(k_gemm, cudaFuncAttributeMaxDynamicSharedMemorySize, SMEM_DYN);

    k_init<<<(CAP_ROWS + 255) / 256, 256>>>();
    cudaMemsetAsync(d_out, 0, (size_t)T_TOK * HDIM * sizeof(float));
    k_round<<<65536, 256>>>(ew);
    k_gate<<<T_TOK / 8, 256>>>(x, gw);
    k_scan<<<1, 1>>>();
    k_gather<<<T_TOK, 128>>>(x);
    k_gemm<<<dim3(HDIM / BN, MAX_TILES), 256, SMEM_DYN>>>(out);
}

// round 10
// speedup vs baseline: 2.1853x; 1.0161x over previous
#include <cuda_runtime.h>
#include <cuda_fp16.h>
#include <cstdint>
#include <cstddef>

#define T_TOK 8192
#define HDIM  4096
#define NEXP  8
#define BM 128
#define BN 256
#define BK 64
#define KT (HDIM / BK)                       // 64
#define CAP_ROWS (2 * T_TOK + NEXP * BM)     // 17408
#define MAX_TILES (CAP_ROWS / BM)            // 136
#define SAS 72                               // smem row stride in halves
#define A_STG (BM * SAS)                     // 9216 halves
#define B_STG (BN * SAS)                     // 18432 halves
#define NSTAGE 4
#define SMEM_DYN (NSTAGE * (A_STG + B_STG) * 2)   // 221184 B

#define W_N4 ((size_t)NEXP * HDIM * HDIM / 4)     // 33554432
#define X_N4 ((size_t)T_TOK * HDIM / 4)           // 8388608
#define GATE_BLOCKS (T_TOK / 8)                   // 1024

// -------- device scratch (static; no runtime allocation) --------
__device__ __half g_w[(size_t)NEXP * HDIM * HDIM];   // fp16-rounded weights
__device__ __half g_xh[(size_t)T_TOK * HDIM];        // fp16 x (contiguous, per token)
__device__ int g_cnt[NEXP], g_fill[NEXP], g_base[NEXP];
__device__ int g_exp0[T_TOK], g_exp1[T_TOK];
__device__ int g_rowtok[CAP_ROWS];                   // grouped row -> token (-1 = pad)
__device__ int g_tile_e[MAX_TILES], g_tile_r[MAX_TILES];
__device__ int g_ntiles;

// -------- helpers --------
__device__ __forceinline__ uint32_t smem_u32(const void* p) {
    uint32_t a;
    asm("{ .reg .u64 t; cvta.to.shared.u64 t, %1; cvt.u32.u64 %0, t; }"
        : "=r"(a) : "l"(p));
    return a;
}

__device__ __forceinline__ void cp16(uint32_t d, const void* s) {
    asm volatile("cp.async.cg.shared.global [%0], [%1], 16;" :: "r"(d), "l"(s));
}

__device__ __forceinline__ void mma16(float* c, const uint32_t* a, const uint32_t* b) {
    asm volatile(
        "mma.sync.aligned.m16n8k16.row.col.f32.f16.f16.f32 "
        "{%0,%1,%2,%3}, {%4,%5,%6,%7}, {%8,%9}, {%0,%1,%2,%3};"
        : "+f"(c[0]), "+f"(c[1]), "+f"(c[2]), "+f"(c[3])
        : "r"(a[0]), "r"(a[1]), "r"(a[2]), "r"(a[3]), "r"(b[0]), "r"(b[1]));
}

__device__ __forceinline__ void ldm4(uint32_t* r, uint32_t addr) {
    asm volatile("ldmatrix.sync.aligned.m8n8.x4.shared.b16 {%0,%1,%2,%3}, [%4];"
                 : "=r"(r[0]), "=r"(r[1]), "=r"(r[2]), "=r"(r[3]) : "r"(addr));
}

__device__ __forceinline__ void red2(float* p, float a, float b) {
    asm volatile("red.global.add.f32 [%0], %1;" :: "l"(p), "f"(a) : "memory");
    asm volatile("red.global.add.f32 [%0], %1;" :: "l"(p + 1), "f"(b) : "memory");
}

__device__ __forceinline__ uint2 cvt4(float4 v) {
    __half2 h0 = __floats2half2_rn(v.x, v.y);
    __half2 h1 = __floats2half2_rn(v.z, v.w);
    uint2 o;
    o.x = *(uint32_t*)&h0;
    o.y = *(uint32_t*)&h1;
    return o;
}

// -------- kernel 1: fused pre-pass --------
// blocks [0, GATE_BLOCKS): gate logits + top-2 (counters pre-zeroed by memset)
// blocks [GATE_BLOCKS, ...): grid-stride fp16 conversion of expert_w and x
__global__ void k_pre(const float* __restrict__ x, const float* __restrict__ gw,
                      const float* __restrict__ ew) {
    if (blockIdx.x < GATE_BLOCKS) {
        int t = blockIdx.x * 8 + (threadIdx.x >> 5);
        int lane = threadIdx.x & 31;
        const float4* xr = (const float4*)(x + (size_t)t * HDIM);
        const float4* gr = (const float4*)gw;
        float acc[NEXP];
#pragma unroll
        for (int e = 0; e < NEXP; e++) acc[e] = 0.f;
        for (int i = lane; i < HDIM / 4; i += 32) {
            float4 xv = xr[i];
#pragma unroll
            for (int e = 0; e < NEXP; e++) {
                float4 wv = gr[e * (HDIM / 4) + i];
                acc[e] += xv.x * wv.x + xv.y * wv.y + xv.z * wv.z + xv.w * wv.w;
            }
        }
#pragma unroll
        for (int o = 16; o > 0; o >>= 1)
#pragma unroll
            for (int e = 0; e < NEXP; e++)
                acc[e] += __shfl_xor_sync(0xFFFFFFFFu, acc[e], o);
        if (lane == 0) {
            float v0 = -1e30f, v1 = -1e30f; int i0 = 0, i1 = 1;
#pragma unroll
            for (int e = 0; e < NEXP; e++) {
                float v = acc[e];
                if (v > v0) { v1 = v0; i1 = i0; v0 = v; i0 = e; }
                else if (v > v1) { v1 = v; i1 = e; }
            }
            g_exp0[t] = i0; g_exp1[t] = i1;
            atomicAdd(&g_cnt[i0], 1);
            atomicAdd(&g_cnt[i1], 1);
        }
        return;
    }
    // conversion part: unified index space [0, W_N4 + X_N4)
    size_t nconv = W_N4 + X_N4;
    size_t nthr = (size_t)(gridDim.x - GATE_BLOCKS) * blockDim.x;
    size_t start = (size_t)(blockIdx.x - GATE_BLOCKS) * blockDim.x + threadIdx.x;
    const float4* wsrc = (const float4*)ew;
    const float4* xsrc = (const float4*)x;
    uint2* wdst = (uint2*)g_w;
    uint2* xdst = (uint2*)g_xh;
    for (size_t i = start; i < nconv; i += nthr) {
        if (i < W_N4) wdst[i] = cvt4(wsrc[i]);
        else          xdst[i - W_N4] = cvt4(xsrc[i - W_N4]);
    }
}

// -------- kernel 2: prefix sum + tile map (1 thread) --------
__global__ void k_scan() {
    if (threadIdx.x != 0 || blockIdx.x != 0) return;
    int total = 0, nt = 0;
    for (int e = 0; e < NEXP; e++) {
        g_base[e] = total;
        int tl = (g_cnt[e] + BM - 1) / BM;
        for (int i = 0; i < tl; i++) { g_tile_e[nt] = e; g_tile_r[nt] = total + i * BM; nt++; }
        total += tl * BM;
    }
    g_ntiles = nt;
}

// -------- kernel 3: assign grouped positions (rowtok pre-set to -1 by memset) --------
__global__ void k_assign() {
    int t = blockIdx.x * blockDim.x + threadIdx.x;
    if (t >= T_TOK) return;
    int e0 = g_exp0[t], e1 = g_exp1[t];
    int p0 = g_base[e0] + atomicAdd(&g_fill[e0], 1);
    int p1 = g_base[e1] + atomicAdd(&g_fill[e1], 1);
    g_rowtok[p0] = t;
    g_rowtok[p1] = t;
}

// -------- kernel 4: grouped GEMM, fp16 m16n8k16 + ldmatrix, 128x256x64, 4-stage --------
// 256 threads = 8 warps in a 2(M) x 4(N) grid, 64x64 per warp.
// A rows loaded indirectly from g_xh via g_rowtok; epilogue scatter-reduces into out.
__global__ void __launch_bounds__(256, 1) k_gemm(float* __restrict__ out) {
    if ((int)blockIdx.y >= g_ntiles) return;
    extern __shared__ __half sm[];
    __half* sAb = sm;                       // 4 stages of A
    __half* sBb = sm + NSTAGE * A_STG;      // 4 stages of B

    int tid = threadIdx.x, lane = tid & 31, warp = tid >> 5;
    int wm = warp >> 2, wn = warp & 3;

    int e = g_tile_e[blockIdx.y];
    int row0 = g_tile_r[blockIdx.y];
    int n0 = blockIdx.x * BN;
    const __half* gB = g_w + (size_t)e * HDIM * HDIM + (size_t)n0 * HDIM;

    // A producer: per-thread indirect row pointers (constant across kt)
    const __half* aSrc[4];
    int aOff[4];
#pragma unroll
    for (int i = 0; i < 4; i++) {
        int ch = tid + i * 256;
        int r = ch >> 3, c = ch & 7;
        int tok = g_rowtok[row0 + r];
        if (tok < 0) tok = 0;
        aSrc[i] = g_xh + (size_t)tok * HDIM + c * 8;
        aOff[i] = r * SAS + c * 8;
    }

    // per-lane ldmatrix offsets (in halves)
    int aLdm = (wm * 64 + (lane & 15)) * SAS + (lane >> 4) * 8;
    int bLdm = (wn * 64 + (lane & 7) + ((lane >> 4) << 3)) * SAS + (((lane >> 3) & 1) << 3);

    float acc[4][8][4];
#pragma unroll
    for (int i = 0; i < 4; i++)
#pragma unroll
        for (int j = 0; j < 8; j++)
#pragma unroll
            for (int k = 0; k < 4; k++) acc[i][j][k] = 0.f;

#define LOAD_STAGE(S, K0) do {                                               \
    __half* _sa = sAb + (S) * A_STG;                                         \
    __half* _sb = sBb + (S) * B_STG;                                         \
    const __half* _gb = gB + (K0);                                           \
    _Pragma("unroll")                                                        \
    for (int _i = 0; _i < 4; _i++)                                           \
        cp16(smem_u32(_sa + aOff[_i]), aSrc[_i] + (K0));                     \
    _Pragma("unroll")                                                        \
    for (int _i = 0; _i < 8; _i++) {                                         \
        int _ch = tid + _i * 256; int _r = _ch >> 3, _c = _ch & 7;           \
        cp16(smem_u32(_sb + _r * SAS + _c * 8), _gb + (size_t)_r * HDIM + _c * 8); \
    }                                                                        \
    asm volatile("cp.async.commit_group;" ::: "memory");                     \
} while (0)

    LOAD_STAGE(0, 0);
    LOAD_STAGE(1, BK);
    LOAD_STAGE(2, 2 * BK);

    for (int kt = 0; kt < KT; kt++) {
        if (kt + 1 == KT) asm volatile("cp.async.wait_group 0;" ::: "memory");
        else              asm volatile("cp.async.wait_group 2;" ::: "memory");
        __syncthreads();

        int cur = kt & (NSTAGE - 1);
        uint32_t aBase = smem_u32(sAb + cur * A_STG + aLdm);
        uint32_t bBase = smem_u32(sBb + cur * B_STG + bLdm);
#pragma unroll
        for (int ks = 0; ks < 4; ks++) {
            uint32_t af[4][4], bf[8][2];
#pragma unroll
            for (int i = 0; i < 4; i++)
                ldm4(af[i], aBase + (i * 16 * SAS + ks * 16) * 2);
#pragma unroll
            for (int jj = 0; jj < 4; jj++) {
                uint32_t r[4];
                ldm4(r, bBase + (jj * 16 * SAS + ks * 16) * 2);
                bf[2 * jj][0] = r[0]; bf[2 * jj][1] = r[1];
                bf[2 * jj + 1][0] = r[2]; bf[2 * jj + 1][1] = r[3];
            }
#pragma unroll
            for (int i = 0; i < 4; i++)
#pragma unroll
                for (int j = 0; j < 8; j++)
                    mma16(acc[i][j], af[i], bf[j]);
        }

        if (kt + 3 < KT) LOAD_STAGE((kt + 3) & (NSTAGE - 1), (kt + 3) * BK);
    }

    // epilogue: scatter-reduce rows into out by token (pad rows skipped)
#pragma unroll
    for (int i = 0; i < 4; i++) {
        int rl = wm * 64 + i * 16 + (lane >> 2);
        int tok0 = g_rowtok[row0 + rl];
        int tok1 = g_rowtok[row0 + rl + 8];
        float* o0 = out + (size_t)tok0 * HDIM;
        float* o1 = out + (size_t)tok1 * HDIM;
#pragma unroll
        for (int j = 0; j < 8; j++) {
            int c0 = n0 + wn * 64 + j * 8 + 2 * (lane & 3);
            if (tok0 >= 0) red2(o0 + c0, acc[i][j][0], acc[i][j][1]);
            if (tok1 >= 0) red2(o1 + c0, acc[i][j][2], acc[i][j][3]);
        }
    }
#undef LOAD_STAGE
}

extern "C" void kernel_launch(void* const* d_in, const int* in_sizes, int n_in,
                              void* d_out, int out_size) {
    const float* x  = (const float*)d_in[0];   // [8192, 4096]
    const float* gw = (const float*)d_in[1];   // [8, 4096]
    const float* ew = (const float*)d_in[2];   // [8, 4096, 4096]
    float* out = (float*)d_out;                // [8192, 4096]
    (void)in_sizes; (void)n_in; (void)out_size;

    cudaFuncSetAttribute(k_gemm, cudaFuncAttributeMaxDynamicSharedMemorySize, SMEM_DYN);

    void *pcnt, *pfill, *prt;
    cudaGetSymbolAddress(&pcnt, g_cnt);
    cudaGetSymbolAddress(&pfill, g_fill);
    cudaGetSymbolAddress(&prt, g_rowtok);

    cudaMemsetAsync(pcnt, 0, NEXP * sizeof(int));
    cudaMemsetAsync(pfill, 0, NEXP * sizeof(int));
    cudaMemsetAsync(prt, 0xFF, CAP_ROWS * sizeof(int));        // -1
    cudaMemsetAsync(d_out, 0, (size_t)T_TOK * HDIM * sizeof(float));

    k_pre<<<GATE_BLOCKS + 65536, 256>>>(x, gw, ew);
    k_scan<<<1, 1>>>();
    k_assign<<<(T_TOK + 255) / 256, 256>>>();
    k_gemm<<<dim3(HDIM / BN, MAX_TILES), 256, SMEM_DYN>>>(out);
}

// round 11
// speedup vs baseline: 2.2844x; 1.0454x over previous
#include <cuda_runtime.h>
#include <cuda_fp16.h>
#include <cstdint>
#include <cstddef>

#define T_TOK 8192
#define HDIM  4096
#define NEXP  8
#define BM 128
#define BN 256
#define BK 64
#define KT (HDIM / BK)                       // 64
#define CAP_ROWS (2 * T_TOK + NEXP * BM)     // 17408
#define MAX_TILES (CAP_ROWS / BM)            // 136
#define SAS 72                               // smem row stride in halves
#define A_STG (BM * SAS)                     // 9216 halves
#define B_STG (BN * SAS)                     // 18432 halves
#define NSTAGE 4
#define SMEM_DYN (NSTAGE * (A_STG + B_STG) * 2)   // 221184 B
#define NTHR 512

#define W_N4 ((size_t)NEXP * HDIM * HDIM / 4)     // 33554432
#define X_N4 ((size_t)T_TOK * HDIM / 4)           // 8388608
#define GATE_BLOCKS (T_TOK / 8)                   // 1024

// -------- device scratch (static; no runtime allocation) --------
__device__ __half g_w[(size_t)NEXP * HDIM * HDIM];   // fp16-rounded weights
__device__ __half g_xh[(size_t)T_TOK * HDIM];        // fp16 x (contiguous, per token)
__device__ int g_cnt[NEXP], g_fill[NEXP], g_base[NEXP];
__device__ int g_exp0[T_TOK], g_exp1[T_TOK];
__device__ int g_rowtok[CAP_ROWS];                   // grouped row -> token (-1 = pad)
__device__ int g_tile_e[MAX_TILES], g_tile_r[MAX_TILES];
__device__ int g_ntiles;

// -------- helpers --------
__device__ __forceinline__ uint32_t smem_u32(const void* p) {
    uint32_t a;
    asm("{ .reg .u64 t; cvta.to.shared.u64 t, %1; cvt.u32.u64 %0, t; }"
        : "=r"(a) : "l"(p));
    return a;
}

__device__ __forceinline__ void cp16(uint32_t d, const void* s) {
    asm volatile("cp.async.cg.shared.global [%0], [%1], 16;" :: "r"(d), "l"(s));
}

__device__ __forceinline__ void mma16(float* c, const uint32_t* a, const uint32_t* b) {
    asm volatile(
        "mma.sync.aligned.m16n8k16.row.col.f32.f16.f16.f32 "
        "{%0,%1,%2,%3}, {%4,%5,%6,%7}, {%8,%9}, {%0,%1,%2,%3};"
        : "+f"(c[0]), "+f"(c[1]), "+f"(c[2]), "+f"(c[3])
        : "r"(a[0]), "r"(a[1]), "r"(a[2]), "r"(a[3]), "r"(b[0]), "r"(b[1]));
}

__device__ __forceinline__ void ldm4(uint32_t* r, uint32_t addr) {
    asm volatile("ldmatrix.sync.aligned.m8n8.x4.shared.b16 {%0,%1,%2,%3}, [%4];"
                 : "=r"(r[0]), "=r"(r[1]), "=r"(r[2]), "=r"(r[3]) : "r"(addr));
}

__device__ __forceinline__ void red2(float* p, float a, float b) {
    asm volatile("red.global.add.f32 [%0], %1;" :: "l"(p), "f"(a) : "memory");
    asm volatile("red.global.add.f32 [%0], %1;" :: "l"(p + 1), "f"(b) : "memory");
}

__device__ __forceinline__ uint2 cvt4(float4 v) {
    __half2 h0 = __floats2half2_rn(v.x, v.y);
    __half2 h1 = __floats2half2_rn(v.z, v.w);
    uint2 o;
    o.x = *(uint32_t*)&h0;
    o.y = *(uint32_t*)&h1;
    return o;
}

// -------- kernel 1: fused pre-pass --------
__global__ void k_pre(const float* __restrict__ x, const float* __restrict__ gw,
                      const float* __restrict__ ew) {
    if (blockIdx.x < GATE_BLOCKS) {
        int t = blockIdx.x * 8 + (threadIdx.x >> 5);
        int lane = threadIdx.x & 31;
        const float4* xr = (const float4*)(x + (size_t)t * HDIM);
        const float4* gr = (const float4*)gw;
        float acc[NEXP];
#pragma unroll
        for (int e = 0; e < NEXP; e++) acc[e] = 0.f;
        for (int i = lane; i < HDIM / 4; i += 32) {
            float4 xv = xr[i];
#pragma unroll
            for (int e = 0; e < NEXP; e++) {
                float4 wv = gr[e * (HDIM / 4) + i];
                acc[e] += xv.x * wv.x + xv.y * wv.y + xv.z * wv.z + xv.w * wv.w;
            }
        }
#pragma unroll
        for (int o = 16; o > 0; o >>= 1)
#pragma unroll
            for (int e = 0; e < NEXP; e++)
                acc[e] += __shfl_xor_sync(0xFFFFFFFFu, acc[e], o);
        if (lane == 0) {
            float v0 = -1e30f, v1 = -1e30f; int i0 = 0, i1 = 1;
#pragma unroll
            for (int e = 0; e < NEXP; e++) {
                float v = acc[e];
                if (v > v0) { v1 = v0; i1 = i0; v0 = v; i0 = e; }
                else if (v > v1) { v1 = v; i1 = e; }
            }
            g_exp0[t] = i0; g_exp1[t] = i1;
            atomicAdd(&g_cnt[i0], 1);
            atomicAdd(&g_cnt[i1], 1);
        }
        return;
    }
    size_t nconv = W_N4 + X_N4;
    size_t nthr = (size_t)(gridDim.x - GATE_BLOCKS) * blockDim.x;
    size_t start = (size_t)(blockIdx.x - GATE_BLOCKS) * blockDim.x + threadIdx.x;
    const float4* wsrc = (const float4*)ew;
    const float4* xsrc = (const float4*)x;
    uint2* wdst = (uint2*)g_w;
    uint2* xdst = (uint2*)g_xh;
    for (size_t i = start; i < nconv; i += nthr) {
        if (i < W_N4) wdst[i] = cvt4(wsrc[i]);
        else          xdst[i - W_N4] = cvt4(xsrc[i - W_N4]);
    }
}

// -------- kernel 2: prefix sum + tile map (1 thread) --------
__global__ void k_scan() {
    if (threadIdx.x != 0 || blockIdx.x != 0) return;
    int total = 0, nt = 0;
    for (int e = 0; e < NEXP; e++) {
        g_base[e] = total;
        int tl = (g_cnt[e] + BM - 1) / BM;
        for (int i = 0; i < tl; i++) { g_tile_e[nt] = e; g_tile_r[nt] = total + i * BM; nt++; }
        total += tl * BM;
    }
    g_ntiles = nt;
}

// -------- kernel 3: assign grouped positions --------
__global__ void k_assign() {
    int t = blockIdx.x * blockDim.x + threadIdx.x;
    if (t >= T_TOK) return;
    int e0 = g_exp0[t], e1 = g_exp1[t];
    int p0 = g_base[e0] + atomicAdd(&g_fill[e0], 1);
    int p1 = g_base[e1] + atomicAdd(&g_fill[e1], 1);
    g_rowtok[p0] = t;
    g_rowtok[p1] = t;
}

// -------- kernel 4: grouped GEMM, fp16 m16n8k16 + ldmatrix, 128x256x64, 4-stage --------
// 512 threads = 16 warps in a 2(M) x 8(N) grid, 64x32 per warp.
__global__ void __launch_bounds__(NTHR, 1) k_gemm(float* __restrict__ out) {
    if ((int)blockIdx.y >= g_ntiles) return;
    extern __shared__ __half sm[];
    __half* sAb = sm;                       // 4 stages of A
    __half* sBb = sm + NSTAGE * A_STG;      // 4 stages of B

    int tid = threadIdx.x, lane = tid & 31, warp = tid >> 5;
    int wm = warp >> 3, wn = warp & 7;      // 2(M) x 8(N)

    int e = g_tile_e[blockIdx.y];
    int row0 = g_tile_r[blockIdx.y];
    int n0 = blockIdx.x * BN;
    const __half* gB = g_w + (size_t)e * HDIM * HDIM + (size_t)n0 * HDIM;

    // A producer: per-thread indirect row pointers (constant across kt)
    const __half* aSrc[2];
    int aOff[2];
#pragma unroll
    for (int i = 0; i < 2; i++) {
        int ch = tid + i * NTHR;
        int r = ch >> 3, c = ch & 7;
        int tok = g_rowtok[row0 + r];
        if (tok < 0) tok = 0;
        aSrc[i] = g_xh + (size_t)tok * HDIM + c * 8;
        aOff[i] = r * SAS + c * 8;
    }

    // per-lane ldmatrix offsets (in halves)
    int aLdm = (wm * 64 + (lane & 15)) * SAS + (lane >> 4) * 8;
    int bLdm = (wn * 32 + (lane & 7) + ((lane >> 4) << 3)) * SAS + (((lane >> 3) & 1) << 3);

    float acc[4][4][4];
#pragma unroll
    for (int i = 0; i < 4; i++)
#pragma unroll
        for (int j = 0; j < 4; j++)
#pragma unroll
            for (int k = 0; k < 4; k++) acc[i][j][k] = 0.f;

#define LOAD_STAGE(S, K0) do {                                               \
    __half* _sa = sAb + (S) * A_STG;                                         \
    __half* _sb = sBb + (S) * B_STG;                                         \
    const __half* _gb = gB + (K0);                                           \
    _Pragma("unroll")                                                        \
    for (int _i = 0; _i < 2; _i++)                                           \
        cp16(smem_u32(_sa + aOff[_i]), aSrc[_i] + (K0));                     \
    _Pragma("unroll")                                                        \
    for (int _i = 0; _i < 4; _i++) {                                         \
        int _ch = tid + _i * NTHR; int _r = _ch >> 3, _c = _ch & 7;          \
        cp16(smem_u32(_sb + _r * SAS + _c * 8), _gb + (size_t)_r * HDIM + _c * 8); \
    }                                                                        \
    asm volatile("cp.async.commit_group;" ::: "memory");                     \
} while (0)

    LOAD_STAGE(0, 0);
    LOAD_STAGE(1, BK);
    LOAD_STAGE(2, 2 * BK);

    for (int kt = 0; kt < KT; kt++) {
        if (kt + 1 == KT) asm volatile("cp.async.wait_group 0;" ::: "memory");
        else              asm volatile("cp.async.wait_group 2;" ::: "memory");
        __syncthreads();

        int cur = kt & (NSTAGE - 1);
        uint32_t aBase = smem_u32(sAb + cur * A_STG + aLdm);
        uint32_t bBase = smem_u32(sBb + cur * B_STG + bLdm);
#pragma unroll
        for (int ks = 0; ks < 4; ks++) {
            uint32_t af[4][4], bf[4][2];
#pragma unroll
            for (int i = 0; i < 4; i++)
                ldm4(af[i], aBase + (i * 16 * SAS + ks * 16) * 2);
#pragma unroll
            for (int jj = 0; jj < 2; jj++) {
                uint32_t r[4];
                ldm4(r, bBase + (jj * 16 * SAS + ks * 16) * 2);
                bf[2 * jj][0] = r[0]; bf[2 * jj][1] = r[1];
                bf[2 * jj + 1][0] = r[2]; bf[2 * jj + 1][1] = r[3];
            }
#pragma unroll
            for (int i = 0; i < 4; i++)
#pragma unroll
                for (int j = 0; j < 4; j++)
                    mma16(acc[i][j], af[i], bf[j]);
        }

        if (kt + 3 < KT) LOAD_STAGE((kt + 3) & (NSTAGE - 1), (kt + 3) * BK);
    }

    // epilogue: scatter-reduce rows into out by token (pad rows skipped)
#pragma unroll
    for (int i = 0; i < 4; i++) {
        int rl = wm * 64 + i * 16 + (lane >> 2);
        int tok0 = g_rowtok[row0 + rl];
        int tok1 = g_rowtok[row0 + rl + 8];
        float* o0 = out + (size_t)tok0 * HDIM;
        float* o1 = out + (size_t)tok1 * HDIM;
#pragma unroll
        for (int j = 0; j < 4; j++) {
            int c0 = n0 + wn * 32 + j * 8 + 2 * (lane & 3);
            if (tok0 >= 0) red2(o0 + c0, acc[i][j][0], acc[i][j][1]);
            if (tok1 >= 0) red2(o1 + c0, acc[i][j][2], acc[i][j][3]);
        }
    }
#undef LOAD_STAGE
}

extern "C" void kernel_launch(void* const* d_in, const int* in_sizes, int n_in,
                              void* d_out, int out_size) {
    const float* x  = (const float*)d_in[0];   // [8192, 4096]
    const float* gw = (const float*)d_in[1];   // [8, 4096]
    const float* ew = (const float*)d_in[2];   // [8, 4096, 4096]
    float* out = (float*)d_out;                // [8192, 4096]
    (void)in_sizes; (void)n_in; (void)out_size;

    cudaFuncSetAttribute(k_gemm, cudaFuncAttributeMaxDynamicSharedMemorySize, SMEM_DYN);

    void *pcnt, *pfill, *prt;
    cudaGetSymbolAddress(&pcnt, g_cnt);
    cudaGetSymbolAddress(&pfill, g_fill);
    cudaGetSymbolAddress(&prt, g_rowtok);

    cudaMemsetAsync(pcnt, 0, NEXP * sizeof(int));
    cudaMemsetAsync(pfill, 0, NEXP * sizeof(int));
    cudaMemsetAsync(prt, 0xFF, CAP_ROWS * sizeof(int));        // -1
    cudaMemsetAsync(d_out, 0, (size_t)T_TOK * HDIM * sizeof(float));

    k_pre<<<GATE_BLOCKS + 65536, 256>>>(x, gw, ew);
    k_scan<<<1, 1>>>();
    k_assign<<<(T_TOK + 255) / 256, 256>>>();
    k_gemm<<<dim3(HDIM / BN, MAX_TILES), NTHR, SMEM_DYN>>>(out);
}